// round 12
// baseline (speedup 1.0000x reference)
#include <cuda_runtime.h>
#include <cuda_bf16.h>
#include <cstdint>

#define NITER   50
#define EPSF    0.1f
#define PCOEF   (1.0f/1.1f)
#define LOGHUGE 69.07755279f   /* log(1e30) */
#define NB      256
#define NN      256
#define KPAD    264            /* padded row length (bf16): 528B stride -> ldmatrix conflict-free */
#define DXC     (1.0f/256.0f)
#define DYC     (1.0f/256.0f)
#define PI2F    1.57079632679489662f
#define NLN2X2  1.38629436112f /* 2*ln2 */

typedef unsigned long long u64;

struct __align__(16) Smem {
    uint16_t Kbuf[NN * KPAD];  // 135168 B: staging for K0_A, then resident K0_B
    uint16_t zbpA[NN], wbpA[NN], zbpB[NN], wbpB[NN];  // bf16 vectors, B-frag (pidx) order
    float part[16][NN];        // A-col partials (iter) / epilogue partials (A rows 0-3, B rows 4-7)
    float zfA[NN], wfA[NN], csA[NN];
    float zfB[NN], wfB[NN], csB[NN];
    float redA[8], redB[8];
};

__device__ __forceinline__ unsigned pack_bf16(float a, float b) {
    __nv_bfloat162 h = __floats2bfloat162_rn(a, b);
    return *reinterpret_cast<unsigned*>(&h);
}
__device__ __forceinline__ uint16_t to_bf16u(float a) {
    __nv_bfloat16 h = __float2bfloat16(a);
    return *reinterpret_cast<uint16_t*>(&h);
}
__device__ __forceinline__ int pidx(int j) {
    return (j & ~15) | (((j & 7) >> 1) << 2) | (((j >> 3) & 1) << 1) | (j & 1);
}
__device__ __forceinline__ void ldmx4(uint32_t addr, uint32_t& r0, uint32_t& r1, uint32_t& r2, uint32_t& r3) {
    asm volatile("ldmatrix.sync.aligned.m8n8.x4.shared.b16 {%0,%1,%2,%3}, [%4];"
                 : "=r"(r0), "=r"(r1), "=r"(r2), "=r"(r3) : "r"(addr));
}
__device__ __forceinline__ void ldmx4t(uint32_t addr, uint32_t& r0, uint32_t& r1, uint32_t& r2, uint32_t& r3) {
    asm volatile("ldmatrix.sync.aligned.m8n8.x4.trans.shared.b16 {%0,%1,%2,%3}, [%4];"
                 : "=r"(r0), "=r"(r1), "=r"(r2), "=r"(r3) : "r"(addr));
}
__device__ __forceinline__ uint32_t movm(uint32_t s) {
    uint32_t d;
    asm("movmatrix.sync.aligned.m8n8.trans.b16 %0, %1;" : "=r"(d) : "r"(s));
    return d;
}
__device__ __forceinline__ void mma_bf16(float& d0, float& d1, float& d2, float& d3,
                                         uint32_t a0, uint32_t a1, uint32_t a2, uint32_t a3,
                                         uint32_t b0, uint32_t b1) {
    asm volatile("mma.sync.aligned.m16n8k16.row.col.f32.bf16.bf16.f32 "
                 "{%0,%1,%2,%3},{%4,%5,%6,%7},{%8,%9},{%0,%1,%2,%3};"
                 : "+f"(d0), "+f"(d1), "+f"(d2), "+f"(d3)
                 : "r"(a0), "r"(a1), "r"(a2), "r"(a3), "r"(b0), "r"(b1));
}
__device__ __forceinline__ u64 lds64(uint32_t addr) {
    u64 p; asm volatile("ld.shared.b64 %0, [%1];" : "=l"(p) : "r"(addr)); return p;
}

// stage K0 = (cos(min(2D,pi/2))+1e-5)^20 as bf16 into Kbuf[i*KPAD+j]
__device__ __forceinline__ void stage_K(const float* __restrict__ Dp, uint16_t* __restrict__ Kb, int t) {
    const float4* __restrict__ D4 = reinterpret_cast<const float4*>(Dp);
    #pragma unroll 4
    for (int k = 0; k < 32; k++) {
        int i4 = t + k * 512;
        float4 d = D4[i4];
        int e = i4 << 2;
        int i = e >> 8, j = e & (NN - 1);
        float c0 = __cosf(fminf(d.x * 2.0f, PI2F)) + 1e-5f;
        float c1 = __cosf(fminf(d.y * 2.0f, PI2F)) + 1e-5f;
        float c2 = __cosf(fminf(d.z * 2.0f, PI2F)) + 1e-5f;
        float c3 = __cosf(fminf(d.w * 2.0f, PI2F)) + 1e-5f;
        float k0 = exp2f(20.0f * __log2f(c0));
        float k1 = exp2f(20.0f * __log2f(c1));
        float k2 = exp2f(20.0f * __log2f(c2));
        float k3 = exp2f(20.0f * __log2f(c3));
        uint2 pk = make_uint2(pack_bf16(k0, k1), pack_bf16(k2, k3));
        *reinterpret_cast<uint2*>(&Kb[i * KPAD + j]) = pk;
    }
}

// epilogue accumulation: row marginal (sans w) and transport (sans w), K recomputed from D
__device__ __forceinline__ void epi_pass(const float* __restrict__ Dp, const float* __restrict__ zf,
                                         float* __restrict__ p4, int t) {
    int row = t & (NN - 1), h = t >> 8;
    const float* __restrict__ dr = Dp + row * NN + h * 128;
    const float* __restrict__ zh = zf + h * 128;
    float racc = 0.f, tlg = 0.f;
    #pragma unroll 4
    for (int c = 0; c < 32; c++) {
        float4 d4 = *reinterpret_cast<const float4*>(dr + c * 4);
        float4 z4 = *reinterpret_cast<const float4*>(zh + c * 4);
        float cc, lg, k0, kz;
        cc = __cosf(fminf(d4.x * 2.0f, PI2F)) + 1e-5f; lg = __log2f(cc); k0 = exp2f(20.0f * lg);
        kz = k0 * z4.x; racc += kz; tlg = fmaf(kz, lg, tlg);
        cc = __cosf(fminf(d4.y * 2.0f, PI2F)) + 1e-5f; lg = __log2f(cc); k0 = exp2f(20.0f * lg);
        kz = k0 * z4.y; racc += kz; tlg = fmaf(kz, lg, tlg);
        cc = __cosf(fminf(d4.z * 2.0f, PI2F)) + 1e-5f; lg = __log2f(cc); k0 = exp2f(20.0f * lg);
        kz = k0 * z4.z; racc += kz; tlg = fmaf(kz, lg, tlg);
        cc = __cosf(fminf(d4.w * 2.0f, PI2F)) + 1e-5f; lg = __log2f(cc); k0 = exp2f(20.0f * lg);
        kz = k0 * z4.w; racc += kz; tlg = fmaf(kz, lg, tlg);
    }
    p4[h * NN + row]          = racc;
    p4[2 * NN + h * NN + row] = -NLN2X2 * tlg;   // sum of K0*z*C
}

__global__ void __launch_bounds__(512, 1)
wfr_kernel(const float* __restrict__ D, float* __restrict__ out)
{
    extern __shared__ char smraw[];
    Smem* sm = reinterpret_cast<Smem*>(smraw);
    const int b = blockIdx.x;                     // batches 2b (A), 2b+1 (B)
    const int t = threadIdx.x;
    const float* __restrict__ DA = D + ((size_t)(2 * b)) * (NN * NN);
    const float* __restrict__ DB = DA + NN * NN;

    const int lane    = t & 31;
    const int wp      = t >> 5;                   // 16 warps
    const int rowbase = wp << 4;
    const bool owner  = (lane & 3) == 0;
    const int  oidx   = rowbase + (lane >> 2);
    const int  q      = lane & 3;

    const uint32_t kb      = (uint32_t)__cvta_generic_to_shared(sm->Kbuf);
    const uint32_t addrRow = kb + 2u * ((rowbase + (lane & 15)) * KPAD + ((lane >> 4) << 3));
    const uint32_t addrCol = kb + 2u * (((lane & 7) + ((lane & 16) >> 1)) * KPAD + rowbase + (lane & 8));
    const uint32_t zAb = (uint32_t)__cvta_generic_to_shared(sm->zbpA) + q * 8;
    const uint32_t zBb = (uint32_t)__cvta_generic_to_shared(sm->zbpB) + q * 8;
    const uint32_t wBb = (uint32_t)__cvta_generic_to_shared(sm->wbpB) + q * 8;
    const uint32_t wAown = (uint32_t)__cvta_generic_to_shared(sm->wbpA) + wp * 32 + q * 8;

    // ---- prologue: stage K0_A, capture A-frags, then stage K0_B (resident) ----
    stage_K(DA, sm->Kbuf, t);
    if (t < NN / 2) {
        reinterpret_cast<uint32_t*>(sm->zbpA)[t] = 0x3F803F80u;
        reinterpret_cast<uint32_t*>(sm->zbpB)[t] = 0x3F803F80u;
    }
    __syncthreads();

    uint32_t A0[16], A1[16], A2[16], A3[16];
    #pragma unroll
    for (int cc = 0; cc < 16; cc++)
        ldmx4(addrRow + cc * 32, A0[cc], A1[cc], A2[cc], A3[cc]);
    __syncthreads();                              // frags captured before overwrite
    stage_K(DB, sm->Kbuf, t);
    __syncthreads();

    float uA0 = 0.f, uA1 = 0.f, uB0 = 0.f, uB1 = 0.f;
    float vB0 = 0.f, vB1 = 0.f, cB0 = 0.f, cB1 = 0.f;
    float vA = 0.f, zAr = 1.f, cAr = 0.f;

    // ---------------- 50 Sinkhorn iterations, two batches fused ----------------
    #pragma unroll 1
    for (int it = 0; it < NITER; it++) {
        // ======== phase 1: row passes ========
        // B row pass (streamed from SMEM)
        {
            float d0 = 0.f, d1 = 0.f, d2 = 0.f, d3 = 0.f;
            float e0 = 0.f, e1 = 0.f, e2 = 0.f, e3 = 0.f;
            #pragma unroll
            for (int cc = 0; cc < 16; cc += 2) {
                u64 p0 = lds64(zBb + cc * 32);
                u64 p1 = lds64(zBb + cc * 32 + 32);
                uint32_t s0, s1, s2, s3;
                ldmx4(addrRow + cc * 32, s0, s1, s2, s3);
                mma_bf16(d0, d1, d2, d3, s0, s1, s2, s3, (uint32_t)p0, (uint32_t)(p0 >> 32));
                ldmx4(addrRow + (cc + 1) * 32, s0, s1, s2, s3);
                mma_bf16(e0, e1, e2, e3, s0, s1, s2, s3, (uint32_t)p1, (uint32_t)(p1 >> 32));
            }
            if (owner) {
                float r0 = d0 + e0, r1 = d2 + e2;
                uB0 += EPSF * fminf(-PCOEF * (11.0f * uB0 + __logf(DYC * r0)), LOGHUGE);
                uB1 += EPSF * fminf(-PCOEF * (11.0f * uB1 + __logf(DYC * r1)), LOGHUGE);
                sm->wbpB[pidx(oidx)]     = to_bf16u(__expf(10.0f * uB0));
                sm->wbpB[pidx(oidx + 8)] = to_bf16u(__expf(10.0f * uB1));
            }
        }
        // A row pass (register frags)
        {
            float d0 = 0.f, d1 = 0.f, d2 = 0.f, d3 = 0.f;
            float e0 = 0.f, e1 = 0.f, e2 = 0.f, e3 = 0.f;
            #pragma unroll
            for (int cc = 0; cc < 16; cc += 2) {
                u64 p0 = lds64(zAb + cc * 32);
                u64 p1 = lds64(zAb + cc * 32 + 32);
                mma_bf16(d0, d1, d2, d3, A0[cc], A1[cc], A2[cc], A3[cc],
                         (uint32_t)p0, (uint32_t)(p0 >> 32));
                mma_bf16(e0, e1, e2, e3, A0[cc + 1], A1[cc + 1], A2[cc + 1], A3[cc + 1],
                         (uint32_t)p1, (uint32_t)(p1 >> 32));
            }
            if (owner) {
                float r0 = d0 + e0, r1 = d2 + e2;
                uA0 += EPSF * fminf(-PCOEF * (11.0f * uA0 + __logf(DYC * r0)), LOGHUGE);
                uA1 += EPSF * fminf(-PCOEF * (11.0f * uA1 + __logf(DYC * r1)), LOGHUGE);
                sm->wbpA[pidx(oidx)]     = to_bf16u(__expf(10.0f * uA0));
                sm->wbpA[pidx(oidx + 8)] = to_bf16u(__expf(10.0f * uA1));
            }
        }
        __syncthreads();

        // ======== phase 2: col passes ========
        // B col pass (streamed transposed ldmatrix)
        {
            float d0 = 0.f, d1 = 0.f, d2 = 0.f, d3 = 0.f;
            float e0 = 0.f, e1 = 0.f, e2 = 0.f, e3 = 0.f;
            #pragma unroll
            for (int cc = 0; cc < 16; cc += 2) {
                u64 p0 = lds64(wBb + cc * 32);
                u64 p1 = lds64(wBb + cc * 32 + 32);
                uint32_t s0, s1, s2, s3;
                ldmx4t(addrCol + cc * (16 * 2 * KPAD), s0, s1, s2, s3);
                mma_bf16(d0, d1, d2, d3, s0, s1, s2, s3, (uint32_t)p0, (uint32_t)(p0 >> 32));
                ldmx4t(addrCol + (cc + 1) * (16 * 2 * KPAD), s0, s1, s2, s3);
                mma_bf16(e0, e1, e2, e3, s0, s1, s2, s3, (uint32_t)p1, (uint32_t)(p1 >> 32));
            }
            if (owner) {
                cB0 = d0 + e0; cB1 = d2 + e2;
                vB0 += EPSF * fminf(-PCOEF * (11.0f * vB0 + __logf(DXC * cB0)), LOGHUGE);
                vB1 += EPSF * fminf(-PCOEF * (11.0f * vB1 + __logf(DXC * cB1)), LOGHUGE);
                sm->zbpB[pidx(oidx)]     = to_bf16u(__expf(10.0f * vB0));
                sm->zbpB[pidx(oidx + 8)] = to_bf16u(__expf(10.0f * vB1));
            }
        }
        // A col pass (movmatrix'd register frags; partial over warp's 16 rows)
        {
            u64 pw = lds64(wAown);
            uint32_t bw0 = (uint32_t)pw, bw1 = (uint32_t)(pw >> 32);
            #pragma unroll
            for (int cc = 0; cc < 16; cc++) {
                float d0 = 0.f, d1 = 0.f, d2 = 0.f, d3 = 0.f;
                mma_bf16(d0, d1, d2, d3,
                         movm(A0[cc]), movm(A2[cc]), movm(A1[cc]), movm(A3[cc]),
                         bw0, bw1);
                if (owner) {
                    sm->part[wp][16 * cc + (lane >> 2)]     = d0;
                    sm->part[wp][16 * cc + 8 + (lane >> 2)] = d2;
                }
            }
        }
        __syncthreads();

        // ======== phase 3: A col reduce + v/z update ========
        if (t < NN) {
            float c = 0.f;
            #pragma unroll
            for (int s = 0; s < 16; s++) c += sm->part[s][t];
            cAr = c;
            vA += EPSF * fminf(-PCOEF * (11.0f * vA + __logf(DXC * c)), LOGHUGE);
            zAr = __expf(10.0f * vA);
            sm->zbpA[pidx(t)] = to_bf16u(zAr);
        }
        __syncthreads();
    }

    // ---- publish final f32 state ----
    if (owner) {
        sm->wfA[oidx]     = __expf(10.0f * uA0);
        sm->wfA[oidx + 8] = __expf(10.0f * uA1);
        sm->wfB[oidx]     = __expf(10.0f * uB0);
        sm->wfB[oidx + 8] = __expf(10.0f * uB1);
        sm->zfB[oidx]     = __expf(10.0f * vB0);
        sm->zfB[oidx + 8] = __expf(10.0f * vB1);
        sm->csB[oidx]     = cB0;
        sm->csB[oidx + 8] = cB1;
    }
    if (t < NN) { sm->zfA[t] = zAr; sm->csA[t] = cAr; }
    __syncthreads();

    // ---- epilogues (K recomputed from D for both batches) ----
    epi_pass(DA, sm->zfA, &sm->part[0][0], t);
    epi_pass(DB, sm->zfB, &sm->part[4][0], t);
    __syncthreads();

    float valA = 0.f, valB = 0.f;
    if (t < NN) {
        {
            float w_  = sm->wfA[t];
            float rm  = DYC * w_ * (sm->part[0][t] + sm->part[1][t]);
            float klr = rm * __logf(rm + 1e-10f) - rm + 1.0f;
            float tp  = w_ * (sm->part[2][t] + sm->part[3][t]) * (DXC * DYC);
            float cm  = DXC * sm->zfA[t] * sm->csA[t];
            float klc = cm * __logf(cm + 1e-10f) - cm + 1.0f;
            valA = klr * DXC + klc * DYC + tp;
        }
        {
            float w_  = sm->wfB[t];
            float rm  = DYC * w_ * (sm->part[4][t] + sm->part[5][t]);
            float klr = rm * __logf(rm + 1e-10f) - rm + 1.0f;
            float tp  = w_ * (sm->part[6][t] + sm->part[7][t]) * (DXC * DYC);
            float cm  = DXC * sm->zfB[t] * sm->csB[t];
            float klc = cm * __logf(cm + 1e-10f) - cm + 1.0f;
            valB = klr * DXC + klc * DYC + tp;
        }
    }
    #pragma unroll
    for (int o = 16; o; o >>= 1) {
        valA += __shfl_down_sync(0xFFFFFFFFu, valA, o);
        valB += __shfl_down_sync(0xFFFFFFFFu, valB, o);
    }
    if (t < NN && lane == 0) { sm->redA[wp] = valA; sm->redB[wp] = valB; }
    __syncthreads();
    if (t == 0) {
        float sA = 0.f, sB = 0.f;
        #pragma unroll
        for (int i = 0; i < 8; i++) { sA += sm->redA[i]; sB += sm->redB[i]; }
        out[2 * b]     = sA;
        out[2 * b + 1] = sB;
    }
}

extern "C" void kernel_launch(void* const* d_in, const int* in_sizes, int n_in,
                              void* d_out, int out_size)
{
    const float* D = (const float*)d_in[0];
    float* out = (float*)d_out;
    (void)in_sizes; (void)n_in; (void)out_size;
    size_t smem = sizeof(Smem);
    cudaFuncSetAttribute(wfr_kernel, cudaFuncAttributeMaxDynamicSharedMemorySize, (int)smem);
    wfr_kernel<<<NB / 2, 512, smem>>>(D, out);
}

// round 13
// speedup vs baseline: 1.1512x; 1.1512x over previous
#include <cuda_runtime.h>
#include <cuda_bf16.h>
#include <cstdint>

#define NITER   50
#define EPSF    0.1f
#define PCOEF   (1.0f/1.1f)
#define LOGHUGE 69.07755279f   /* log(1e30) */
#define NB      256
#define NN      256
#define KPAD    264            /* padded row length (bf16): 528B stride -> ldmatrix conflict-free */
#define DXC     (1.0f/256.0f)
#define DYC     (1.0f/256.0f)
#define PI2F    1.57079632679489662f

typedef unsigned long long u64;

struct __align__(16) Smem {
    uint16_t K0[NN * KPAD];   // 135168 B, bf16 kernel matrix K0 = exp(-C/eps)
    float z[NN];              // f32 z (epilogue only)
    float w[NN];              // f32 w (epilogue only)
    float csave[NN];          // final col sums (epilogue only)
    uint16_t zbp[NN];         // packed bf16 z in chunk-pair B-frag (pidx2) order
    uint16_t wbp[NN];         // packed bf16 w in pidx2 order
    float part[4][NN];        // epilogue scratch
    float red[16];
};

__device__ __forceinline__ unsigned pack_bf16(float a, float b) {
    __nv_bfloat162 h = __floats2bfloat162_rn(a, b);
    return *reinterpret_cast<unsigned*>(&h);
}
__device__ __forceinline__ uint16_t to_bf16u(float a) {
    __nv_bfloat16 h = __float2bfloat16(a);
    return *reinterpret_cast<uint16_t*>(&h);
}
// chunk-pair packed index (proven in R11): pair block of 32 values; thread q's 16B:
// [chunk even: h0e0,h0e1,h1e0,h1e1][chunk odd: same]
__device__ __forceinline__ int pidx2(int j) {
    int chunk = j >> 4;
    int pair  = chunk >> 1;
    int odd   = chunk & 1;
    int q     = (j & 7) >> 1;
    int h     = (j >> 3) & 1;
    int e     = j & 1;
    return pair * 32 + q * 8 + odd * 4 + h * 2 + e;
}
__device__ __forceinline__ void ldmx4(uint32_t addr, uint32_t& r0, uint32_t& r1, uint32_t& r2, uint32_t& r3) {
    asm volatile("ldmatrix.sync.aligned.m8n8.x4.shared.b16 {%0,%1,%2,%3}, [%4];"
                 : "=r"(r0), "=r"(r1), "=r"(r2), "=r"(r3) : "r"(addr));
}
__device__ __forceinline__ void ldmx4t(uint32_t addr, uint32_t& r0, uint32_t& r1, uint32_t& r2, uint32_t& r3) {
    asm volatile("ldmatrix.sync.aligned.m8n8.x4.trans.shared.b16 {%0,%1,%2,%3}, [%4];"
                 : "=r"(r0), "=r"(r1), "=r"(r2), "=r"(r3) : "r"(addr));
}
__device__ __forceinline__ void mma_bf16(float& d0, float& d1, float& d2, float& d3,
                                         uint32_t a0, uint32_t a1, uint32_t a2, uint32_t a3,
                                         uint32_t b0, uint32_t b1) {
    asm volatile("mma.sync.aligned.m16n8k16.row.col.f32.bf16.bf16.f32 "
                 "{%0,%1,%2,%3},{%4,%5,%6,%7},{%8,%9},{%0,%1,%2,%3};"
                 : "+f"(d0), "+f"(d1), "+f"(d2), "+f"(d3)
                 : "r"(a0), "r"(a1), "r"(a2), "r"(a3), "r"(b0), "r"(b1));
}
__device__ __forceinline__ uint4 lds128(uint32_t addr) {
    uint4 v;
    asm volatile("ld.shared.v4.b32 {%0,%1,%2,%3}, [%4];"
                 : "=r"(v.x), "=r"(v.y), "=r"(v.z), "=r"(v.w) : "r"(addr));
    return v;
}

__global__ void __launch_bounds__(512, 1)
wfr_kernel(const float* __restrict__ D, float* __restrict__ out)
{
    extern __shared__ char smraw[];
    Smem* sm = reinterpret_cast<Smem*>(smraw);
    const int b = blockIdx.x;
    const int t = threadIdx.x;
    const float* __restrict__ Db = D + (size_t)b * (NN * NN);

    // ---------------- Prologue: K0 = (cos(min(2D,pi/2)) + 1e-5)^20  (bf16, SMEM) ---------
    {
        const float4* __restrict__ D4 = reinterpret_cast<const float4*>(Db);
        #pragma unroll 4
        for (int k = 0; k < 32; k++) {
            int i4 = t + k * 512;
            float4 d = D4[i4];
            int e = i4 << 2;
            int i = e >> 8, j = e & (NN - 1);
            float c0 = __cosf(fminf(d.x * 2.0f, PI2F)) + 1e-5f;
            float c1 = __cosf(fminf(d.y * 2.0f, PI2F)) + 1e-5f;
            float c2 = __cosf(fminf(d.z * 2.0f, PI2F)) + 1e-5f;
            float c3 = __cosf(fminf(d.w * 2.0f, PI2F)) + 1e-5f;
            float k0 = exp2f(20.0f * __log2f(c0));
            float k1 = exp2f(20.0f * __log2f(c1));
            float k2 = exp2f(20.0f * __log2f(c2));
            float k3 = exp2f(20.0f * __log2f(c3));
            uint2 pk = make_uint2(pack_bf16(k0, k1), pack_bf16(k2, k3));
            *reinterpret_cast<uint2*>(&sm->K0[i * KPAD + j]) = pk;
        }
        if (t < NN / 2) reinterpret_cast<uint32_t*>(sm->zbp)[t] = 0x3F803F80u; // z = 1.0
    }
    __syncthreads();

    const int lane    = t & 31;
    const int wp      = t >> 5;         // 16 warps
    const int rowbase = wp << 4;        // 16 rows per warp
    const bool owner  = (lane & 3) == 0;
    const int  oidx   = rowbase + (lane >> 2);
    const int  q      = lane & 3;

    uint16_t* zb16 = sm->zbp;
    uint16_t* wb16 = sm->wbp;
    const int po0 = pidx2(oidx), po1 = pidx2(oidx + 8);

    const uint32_t k0base = (uint32_t)__cvta_generic_to_shared(sm->K0);
    const uint32_t addrRow = k0base + 2u * ((rowbase + (lane & 15)) * KPAD + ((lane >> 4) << 3));
    const uint32_t addrCol = k0base + 2u * (((lane & 7) + ((lane & 16) >> 1)) * KPAD + rowbase + (lane & 8));
    const uint32_t zbase = (uint32_t)__cvta_generic_to_shared(sm->zbp) + q * 16;
    const uint32_t wbase = (uint32_t)__cvta_generic_to_shared(sm->wbp) + q * 16;

    // ---- load row-pass A fragments ONCE (K0 is iteration-invariant) ----
    uint32_t A0[16], A1[16], A2[16], A3[16];
    #pragma unroll
    for (int cc = 0; cc < 16; cc++)
        ldmx4(addrRow + cc * 32, A0[cc], A1[cc], A2[cc], A3[cc]);

    float u0 = 0.0f, u1 = 0.0f;         // owner-lane row potentials
    float w0f = 1.0f, w1f = 1.0f;
    float v0 = 0.0f, v1 = 0.0f;         // owner-lane col potentials
    float z0f = 1.0f, z1f = 1.0f, c0s = 0.0f, c1s = 0.0f;

    // ---------------- 50 Sinkhorn iterations (eager rescale, tensor-core matvecs) --------
    #pragma unroll 1
    for (int it = 0; it < NITER; it++) {
        // ---- row pass: r = K0 z (A-frags in registers; B via one LDS.128 per chunk pair;
        //      R6's two accumulator chains) ----
        {
            float d0 = 0.f, d1 = 0.f, d2 = 0.f, d3 = 0.f;
            float e0 = 0.f, e1 = 0.f, e2 = 0.f, e3 = 0.f;
            #pragma unroll
            for (int p = 0; p < 8; p++) {
                uint4 bb = lds128(zbase + p * 64);
                int cc = 2 * p;
                mma_bf16(d0, d1, d2, d3, A0[cc], A1[cc], A2[cc], A3[cc], bb.x, bb.y);
                mma_bf16(e0, e1, e2, e3, A0[cc + 1], A1[cc + 1], A2[cc + 1], A3[cc + 1], bb.z, bb.w);
            }
            float r0 = d0 + e0;      // row oidx
            float r1 = d2 + e2;      // row oidx+8
            float la0 = fminf(-PCOEF * (11.0f * u0 + __logf(DYC * r0)), LOGHUGE);
            float la1 = fminf(-PCOEF * (11.0f * u1 + __logf(DYC * r1)), LOGHUGE);
            u0 += EPSF * la0;
            u1 += EPSF * la1;
            w0f = __expf(10.0f * u0);
            w1f = __expf(10.0f * u1);
            if (owner) {
                wb16[po0] = to_bf16u(w0f);
                wb16[po1] = to_bf16u(w1f);
            }
        }
        __syncthreads();

        // ---- col pass: c = K0^T w (streamed transposed ldmatrix; B via LDS.128) ----
        {
            float d0 = 0.f, d1 = 0.f, d2 = 0.f, d3 = 0.f;
            float e0 = 0.f, e1 = 0.f, e2 = 0.f, e3 = 0.f;
            #pragma unroll
            for (int p = 0; p < 8; p++) {
                uint4 bb = lds128(wbase + p * 64);
                int cc = 2 * p;
                uint32_t a0, a1, a2, a3;
                ldmx4t(addrCol + cc * (16 * 2 * KPAD), a0, a1, a2, a3);
                mma_bf16(d0, d1, d2, d3, a0, a1, a2, a3, bb.x, bb.y);
                ldmx4t(addrCol + (cc + 1) * (16 * 2 * KPAD), a0, a1, a2, a3);
                mma_bf16(e0, e1, e2, e3, a0, a1, a2, a3, bb.z, bb.w);
            }
            float c0 = d0 + e0;      // col oidx
            float c1 = d2 + e2;      // col oidx+8
            c0s = c0; c1s = c1;
            float lb0 = fminf(-PCOEF * (11.0f * v0 + __logf(DXC * c0)), LOGHUGE);
            float lb1 = fminf(-PCOEF * (11.0f * v1 + __logf(DXC * c1)), LOGHUGE);
            v0 += EPSF * lb0;
            v1 += EPSF * lb1;
            z0f = __expf(10.0f * v0);
            z1f = __expf(10.0f * v1);
            if (owner) {
                zb16[po0] = to_bf16u(z0f);
                zb16[po1] = to_bf16u(z1f);
            }
        }
        __syncthreads();
    }

    // publish final f32 state for the epilogue
    if (owner) {
        sm->w[oidx]     = w0f;  sm->w[oidx + 8]     = w1f;
        sm->z[oidx]     = z0f;  sm->z[oidx + 8]     = z1f;
        sm->csave[oidx] = c0s;  sm->csave[oidx + 8] = c1s;
    }
    __syncthreads();

    // ---------------- Epilogue: marginals + transport --------------------------------
    const int row = t & (NN - 1);
    const int h   = t >> 8;
    {
        const uint16_t* __restrict__ kr = sm->K0 + row * KPAD + h * 128;
        const float*    __restrict__ zh = sm->z + h * 128;
        const float*    __restrict__ dr = Db + row * NN + h * 128;
        float racc = 0.f, tacc = 0.f;
        #pragma unroll 4
        for (int c = 0; c < 16; c++) {
            uint4  k4 = *reinterpret_cast<const uint4*>(kr + c * 8);
            float4 z0 = *reinterpret_cast<const float4*>(zh + c * 8);
            float4 z1 = *reinterpret_cast<const float4*>(zh + c * 8 + 4);
            float4 d0 = *reinterpret_cast<const float4*>(dr + c * 8);
            float4 d1 = *reinterpret_cast<const float4*>(dr + c * 8 + 4);

            float kz, cc, Cv;
            kz = __uint_as_float(k4.x << 16)          * z0.x; racc += kz;
            cc = __cosf(fminf(d0.x * 2.0f, PI2F)) + 1e-5f; Cv = -2.0f * __logf(cc); tacc = fmaf(kz, Cv, tacc);
            kz = __uint_as_float(k4.x & 0xFFFF0000u)  * z0.y; racc += kz;
            cc = __cosf(fminf(d0.y * 2.0f, PI2F)) + 1e-5f; Cv = -2.0f * __logf(cc); tacc = fmaf(kz, Cv, tacc);
            kz = __uint_as_float(k4.y << 16)          * z0.z; racc += kz;
            cc = __cosf(fminf(d0.z * 2.0f, PI2F)) + 1e-5f; Cv = -2.0f * __logf(cc); tacc = fmaf(kz, Cv, tacc);
            kz = __uint_as_float(k4.y & 0xFFFF0000u)  * z0.w; racc += kz;
            cc = __cosf(fminf(d0.w * 2.0f, PI2F)) + 1e-5f; Cv = -2.0f * __logf(cc); tacc = fmaf(kz, Cv, tacc);
            kz = __uint_as_float(k4.z << 16)          * z1.x; racc += kz;
            cc = __cosf(fminf(d1.x * 2.0f, PI2F)) + 1e-5f; Cv = -2.0f * __logf(cc); tacc = fmaf(kz, Cv, tacc);
            kz = __uint_as_float(k4.z & 0xFFFF0000u)  * z1.y; racc += kz;
            cc = __cosf(fminf(d1.y * 2.0f, PI2F)) + 1e-5f; Cv = -2.0f * __logf(cc); tacc = fmaf(kz, Cv, tacc);
            kz = __uint_as_float(k4.w << 16)          * z1.z; racc += kz;
            cc = __cosf(fminf(d1.z * 2.0f, PI2F)) + 1e-5f; Cv = -2.0f * __logf(cc); tacc = fmaf(kz, Cv, tacc);
            kz = __uint_as_float(k4.w & 0xFFFF0000u)  * z1.w; racc += kz;
            cc = __cosf(fminf(d1.w * 2.0f, PI2F)) + 1e-5f; Cv = -2.0f * __logf(cc); tacc = fmaf(kz, Cv, tacc);
        }
        sm->part[h][row]     = racc;
        sm->part[2 + h][row] = tacc;
    }
    __syncthreads();

    float val = 0.0f;
    if (t < NN) {
        float w_  = sm->w[t];
        float rm  = DYC * w_ * (sm->part[0][t] + sm->part[1][t]);
        float klr = rm * __logf(rm + 1e-10f) - rm + 1.0f;
        float tp  = w_ * (sm->part[2][t] + sm->part[3][t]) * (DXC * DYC);
        float cm  = DXC * sm->z[t] * sm->csave[t];
        float klc = cm * __logf(cm + 1e-10f) - cm + 1.0f;
        val = klr * DXC + klc * DYC + tp;
    }
    #pragma unroll
    for (int o = 16; o; o >>= 1) val += __shfl_down_sync(0xFFFFFFFFu, val, o);
    if (t < NN && lane == 0) sm->red[wp] = val;
    __syncthreads();
    if (t == 0) {
        float s = 0.0f;
        #pragma unroll
        for (int i = 0; i < 8; i++) s += sm->red[i];
        out[b] = s;
    }
}

extern "C" void kernel_launch(void* const* d_in, const int* in_sizes, int n_in,
                              void* d_out, int out_size)
{
    const float* D = (const float*)d_in[0];
    float* out = (float*)d_out;
    (void)in_sizes; (void)n_in; (void)out_size;
    size_t smem = sizeof(Smem);
    cudaFuncSetAttribute(wfr_kernel, cudaFuncAttributeMaxDynamicSharedMemorySize, (int)smem);
    wfr_kernel<<<NB, 512, smem>>>(D, out);
}

// round 14
// speedup vs baseline: 1.2304x; 1.0688x over previous
#include <cuda_runtime.h>
#include <cuda_bf16.h>
#include <cstdint>

#define NITER   50
#define EPSF    0.1f
#define PCOEF   (1.0f/1.1f)
#define LOGHUGE 69.07755279f   /* log(1e30) */
#define NB      256
#define NN      256
#define KPAD    264            /* padded row length (bf16): 528B stride -> ldmatrix conflict-free */
#define DXC     (1.0f/256.0f)
#define DYC     (1.0f/256.0f)
#define PI2F    1.57079632679489662f
#define CSTR    (16 * 2 * KPAD)   /* byte stride between col-pass i-chunks */

typedef unsigned long long u64;

struct __align__(16) Smem {
    uint16_t K0[NN * KPAD];   // 135168 B, bf16 kernel matrix K0 = exp(-C/eps)
    float z[NN];              // f32 z (epilogue only)
    float w[NN];              // f32 w (epilogue only)
    float csave[NN];          // final col sums (epilogue only)
    uint16_t zbp[NN];         // packed bf16 z in B-frag (pidx) order
    uint16_t wbp[NN];         // packed bf16 w in pidx order
    float part[4][NN];        // epilogue scratch
    float red[16];
};

__device__ __forceinline__ unsigned pack_bf16(float a, float b) {
    __nv_bfloat162 h = __floats2bfloat162_rn(a, b);
    return *reinterpret_cast<unsigned*>(&h);
}
__device__ __forceinline__ uint16_t to_bf16u(float a) {
    __nv_bfloat16 h = __float2bfloat16(a);
    return *reinterpret_cast<uint16_t*>(&h);
}
// packed B-frag index for column/row j: (chunk=j>>4, q=(j&7)>>1, h=(j>>3)&1, e=j&1)
__device__ __forceinline__ int pidx(int j) {
    return (j & ~15) | (((j & 7) >> 1) << 2) | (((j >> 3) & 1) << 1) | (j & 1);
}
__device__ __forceinline__ void ldmx4(uint32_t addr, uint32_t& r0, uint32_t& r1, uint32_t& r2, uint32_t& r3) {
    asm volatile("ldmatrix.sync.aligned.m8n8.x4.shared.b16 {%0,%1,%2,%3}, [%4];"
                 : "=r"(r0), "=r"(r1), "=r"(r2), "=r"(r3) : "r"(addr));
}
__device__ __forceinline__ void ldmx4t(uint32_t addr, uint32_t& r0, uint32_t& r1, uint32_t& r2, uint32_t& r3) {
    asm volatile("ldmatrix.sync.aligned.m8n8.x4.trans.shared.b16 {%0,%1,%2,%3}, [%4];"
                 : "=r"(r0), "=r"(r1), "=r"(r2), "=r"(r3) : "r"(addr));
}
__device__ __forceinline__ void mma_bf16(float& d0, float& d1, float& d2, float& d3,
                                         uint32_t a0, uint32_t a1, uint32_t a2, uint32_t a3,
                                         uint32_t b0, uint32_t b1) {
    asm volatile("mma.sync.aligned.m16n8k16.row.col.f32.bf16.bf16.f32 "
                 "{%0,%1,%2,%3},{%4,%5,%6,%7},{%8,%9},{%0,%1,%2,%3};"
                 : "+f"(d0), "+f"(d1), "+f"(d2), "+f"(d3)
                 : "r"(a0), "r"(a1), "r"(a2), "r"(a3), "r"(b0), "r"(b1));
}
__device__ __forceinline__ u64 lds64(uint32_t addr) {
    u64 p; asm volatile("ld.shared.b64 %0, [%1];" : "=l"(p) : "r"(addr)); return p;
}

__global__ void __launch_bounds__(512, 1)
wfr_kernel(const float* __restrict__ D, float* __restrict__ out)
{
    extern __shared__ char smraw[];
    Smem* sm = reinterpret_cast<Smem*>(smraw);
    const int b = blockIdx.x;
    const int t = threadIdx.x;
    const float* __restrict__ Db = D + (size_t)b * (NN * NN);

    // ---------------- Prologue: K0 = (cos(min(2D,pi/2)) + 1e-5)^20  (bf16, SMEM) ---------
    {
        const float4* __restrict__ D4 = reinterpret_cast<const float4*>(Db);
        #pragma unroll 4
        for (int k = 0; k < 32; k++) {
            int i4 = t + k * 512;
            float4 d = D4[i4];
            int e = i4 << 2;
            int i = e >> 8, j = e & (NN - 1);
            float c0 = __cosf(fminf(d.x * 2.0f, PI2F)) + 1e-5f;
            float c1 = __cosf(fminf(d.y * 2.0f, PI2F)) + 1e-5f;
            float c2 = __cosf(fminf(d.z * 2.0f, PI2F)) + 1e-5f;
            float c3 = __cosf(fminf(d.w * 2.0f, PI2F)) + 1e-5f;
            float k0 = exp2f(20.0f * __log2f(c0));
            float k1 = exp2f(20.0f * __log2f(c1));
            float k2 = exp2f(20.0f * __log2f(c2));
            float k3 = exp2f(20.0f * __log2f(c3));
            uint2 pk = make_uint2(pack_bf16(k0, k1), pack_bf16(k2, k3));
            *reinterpret_cast<uint2*>(&sm->K0[i * KPAD + j]) = pk;
        }
        if (t < NN / 2) reinterpret_cast<uint32_t*>(sm->zbp)[t] = 0x3F803F80u; // z = 1.0
    }
    __syncthreads();

    const int lane    = t & 31;
    const int wp      = t >> 5;         // 16 warps
    const int rowbase = wp << 4;        // 16 rows per warp
    const bool owner  = (lane & 3) == 0;
    const int  oidx   = rowbase + (lane >> 2);
    const int  q      = lane & 3;

    uint16_t* zb16 = sm->zbp;
    uint16_t* wb16 = sm->wbp;
    const int po0 = pidx(oidx), po1 = pidx(oidx + 8);

    const uint32_t k0base = (uint32_t)__cvta_generic_to_shared(sm->K0);
    const uint32_t addrRow = k0base + 2u * ((rowbase + (lane & 15)) * KPAD + ((lane >> 4) << 3));
    const uint32_t addrCol = k0base + 2u * (((lane & 7) + ((lane & 16) >> 1)) * KPAD + rowbase + (lane & 8));
    const uint32_t zbase = (uint32_t)__cvta_generic_to_shared(sm->zbp) + q * 8;
    const uint32_t wbase = (uint32_t)__cvta_generic_to_shared(sm->wbp) + q * 8;

    // ---- load row-pass A fragments ONCE (K0 is iteration-invariant) ----
    uint32_t A0[16], A1[16], A2[16], A3[16];
    #pragma unroll
    for (int cc = 0; cc < 16; cc++)
        ldmx4(addrRow + cc * 32, A0[cc], A1[cc], A2[cc], A3[cc]);

    float u0 = 0.0f, u1 = 0.0f;         // owner-lane row potentials
    float w0f = 1.0f, w1f = 1.0f;
    float v0 = 0.0f, v1 = 0.0f;         // owner-lane col potentials
    float z0f = 1.0f, z1f = 1.0f, c0s = 0.0f, c1s = 0.0f;

    // ---------------- 50 Sinkhorn iterations (eager rescale, tensor-core matvecs) --------
    #pragma unroll 1
    for (int it = 0; it < NITER; it++) {
        // ---- row pass: r = K0 z (A-frags in registers, B via LDS.64) ----
        uint32_t f0, f1, f2, f3;        // col-pass chunk-0 prefetch (K0 = const, barrier-safe)
        {
            float d0 = 0.f, d1 = 0.f, d2 = 0.f, d3 = 0.f;
            float e0 = 0.f, e1 = 0.f, e2 = 0.f, e3 = 0.f;
            #pragma unroll
            for (int cc = 0; cc < 16; cc += 2) {
                u64 p0 = lds64(zbase + cc * 32);
                u64 p1 = lds64(zbase + cc * 32 + 32);
                mma_bf16(d0, d1, d2, d3, A0[cc], A1[cc], A2[cc], A3[cc],
                         (uint32_t)p0, (uint32_t)(p0 >> 32));
                mma_bf16(e0, e1, e2, e3, A0[cc + 1], A1[cc + 1], A2[cc + 1], A3[cc + 1],
                         (uint32_t)p1, (uint32_t)(p1 >> 32));
            }
            // hoisted col-pass prefetch: overlaps the scalar chain + barrier drain
            ldmx4t(addrCol, f0, f1, f2, f3);

            float r0 = d0 + e0;      // row oidx
            float r1 = d2 + e2;      // row oidx+8
            float la0 = fminf(-PCOEF * (11.0f * u0 + __logf(DYC * r0)), LOGHUGE);
            float la1 = fminf(-PCOEF * (11.0f * u1 + __logf(DYC * r1)), LOGHUGE);
            u0 += EPSF * la0;
            u1 += EPSF * la1;
            w0f = __expf(10.0f * u0);
            w1f = __expf(10.0f * u1);
            if (owner) {
                wb16[po0] = to_bf16u(w0f);
                wb16[po1] = to_bf16u(w1f);
            }
        }
        __syncthreads();

        // ---- col pass: c = K0^T w (1-deep ldsm software pipeline; B via LDS.64) ----
        {
            float d0 = 0.f, d1 = 0.f, d2 = 0.f, d3 = 0.f;
            float e0 = 0.f, e1 = 0.f, e2 = 0.f, e3 = 0.f;
            #pragma unroll
            for (int p = 0; p < 8; p++) {
                int cc = 2 * p;
                u64 p0 = lds64(wbase + cc * 32);
                u64 p1 = lds64(wbase + cc * 32 + 32);
                uint32_t g0, g1, g2, g3;
                ldmx4t(addrCol + (cc + 1) * CSTR, g0, g1, g2, g3);
                mma_bf16(d0, d1, d2, d3, f0, f1, f2, f3,
                         (uint32_t)p0, (uint32_t)(p0 >> 32));
                if (p < 7)
                    ldmx4t(addrCol + (cc + 2) * CSTR, f0, f1, f2, f3);
                mma_bf16(e0, e1, e2, e3, g0, g1, g2, g3,
                         (uint32_t)p1, (uint32_t)(p1 >> 32));
            }
            float c0 = d0 + e0;      // col oidx
            float c1 = d2 + e2;      // col oidx+8
            c0s = c0; c1s = c1;
            float lb0 = fminf(-PCOEF * (11.0f * v0 + __logf(DXC * c0)), LOGHUGE);
            float lb1 = fminf(-PCOEF * (11.0f * v1 + __logf(DXC * c1)), LOGHUGE);
            v0 += EPSF * lb0;
            v1 += EPSF * lb1;
            z0f = __expf(10.0f * v0);
            z1f = __expf(10.0f * v1);
            if (owner) {
                zb16[po0] = to_bf16u(z0f);
                zb16[po1] = to_bf16u(z1f);
            }
        }
        __syncthreads();
    }

    // publish final f32 state for the epilogue
    if (owner) {
        sm->w[oidx]     = w0f;  sm->w[oidx + 8]     = w1f;
        sm->z[oidx]     = z0f;  sm->z[oidx + 8]     = z1f;
        sm->csave[oidx] = c0s;  sm->csave[oidx + 8] = c1s;
    }
    __syncthreads();

    // ---------------- Epilogue: marginals + transport --------------------------------
    const int row = t & (NN - 1);
    const int h   = t >> 8;
    {
        const uint16_t* __restrict__ kr = sm->K0 + row * KPAD + h * 128;
        const float*    __restrict__ zh = sm->z + h * 128;
        const float*    __restrict__ dr = Db + row * NN + h * 128;
        float racc = 0.f, tacc = 0.f;
        #pragma unroll 4
        for (int c = 0; c < 16; c++) {
            uint4  k4 = *reinterpret_cast<const uint4*>(kr + c * 8);
            float4 z0 = *reinterpret_cast<const float4*>(zh + c * 8);
            float4 z1 = *reinterpret_cast<const float4*>(zh + c * 8 + 4);
            float4 d0 = *reinterpret_cast<const float4*>(dr + c * 8);
            float4 d1 = *reinterpret_cast<const float4*>(dr + c * 8 + 4);

            float kz, cc, Cv;
            kz = __uint_as_float(k4.x << 16)          * z0.x; racc += kz;
            cc = __cosf(fminf(d0.x * 2.0f, PI2F)) + 1e-5f; Cv = -2.0f * __logf(cc); tacc = fmaf(kz, Cv, tacc);
            kz = __uint_as_float(k4.x & 0xFFFF0000u)  * z0.y; racc += kz;
            cc = __cosf(fminf(d0.y * 2.0f, PI2F)) + 1e-5f; Cv = -2.0f * __logf(cc); tacc = fmaf(kz, Cv, tacc);
            kz = __uint_as_float(k4.y << 16)          * z0.z; racc += kz;
            cc = __cosf(fminf(d0.z * 2.0f, PI2F)) + 1e-5f; Cv = -2.0f * __logf(cc); tacc = fmaf(kz, Cv, tacc);
            kz = __uint_as_float(k4.y & 0xFFFF0000u)  * z0.w; racc += kz;
            cc = __cosf(fminf(d0.w * 2.0f, PI2F)) + 1e-5f; Cv = -2.0f * __logf(cc); tacc = fmaf(kz, Cv, tacc);
            kz = __uint_as_float(k4.z << 16)          * z1.x; racc += kz;
            cc = __cosf(fminf(d1.x * 2.0f, PI2F)) + 1e-5f; Cv = -2.0f * __logf(cc); tacc = fmaf(kz, Cv, tacc);
            kz = __uint_as_float(k4.z & 0xFFFF0000u)  * z1.y; racc += kz;
            cc = __cosf(fminf(d1.y * 2.0f, PI2F)) + 1e-5f; Cv = -2.0f * __logf(cc); tacc = fmaf(kz, Cv, tacc);
            kz = __uint_as_float(k4.w << 16)          * z1.z; racc += kz;
            cc = __cosf(fminf(d1.z * 2.0f, PI2F)) + 1e-5f; Cv = -2.0f * __logf(cc); tacc = fmaf(kz, Cv, tacc);
            kz = __uint_as_float(k4.w & 0xFFFF0000u)  * z1.w; racc += kz;
            cc = __cosf(fminf(d1.w * 2.0f, PI2F)) + 1e-5f; Cv = -2.0f * __logf(cc); tacc = fmaf(kz, Cv, tacc);
        }
        sm->part[h][row]     = racc;
        sm->part[2 + h][row] = tacc;
    }
    __syncthreads();

    float val = 0.0f;
    if (t < NN) {
        float w_  = sm->w[t];
        float rm  = DYC * w_ * (sm->part[0][t] + sm->part[1][t]);
        float klr = rm * __logf(rm + 1e-10f) - rm + 1.0f;
        float tp  = w_ * (sm->part[2][t] + sm->part[3][t]) * (DXC * DYC);
        float cm  = DXC * sm->z[t] * sm->csave[t];
        float klc = cm * __logf(cm + 1e-10f) - cm + 1.0f;
        val = klr * DXC + klc * DYC + tp;
    }
    #pragma unroll
    for (int o = 16; o; o >>= 1) val += __shfl_down_sync(0xFFFFFFFFu, val, o);
    if (t < NN && lane == 0) sm->red[wp] = val;
    __syncthreads();
    if (t == 0) {
        float s = 0.0f;
        #pragma unroll
        for (int i = 0; i < 8; i++) s += sm->red[i];
        out[b] = s;
    }
}

extern "C" void kernel_launch(void* const* d_in, const int* in_sizes, int n_in,
                              void* d_out, int out_size)
{
    const float* D = (const float*)d_in[0];
    float* out = (float*)d_out;
    (void)in_sizes; (void)n_in; (void)out_size;
    size_t smem = sizeof(Smem);
    cudaFuncSetAttribute(wfr_kernel, cudaFuncAttributeMaxDynamicSharedMemorySize, (int)smem);
    wfr_kernel<<<NB, 512, smem>>>(D, out);
}

// round 15
// speedup vs baseline: 1.2564x; 1.0211x over previous
#include <cuda_runtime.h>
#include <cuda_bf16.h>
#include <cstdint>

#define NITER   50
#define NB      256
#define NN      256
#define KPAD    264            /* padded row length (bf16): 528B stride -> ldmatrix conflict-free */
#define DXC     (1.0f/256.0f)
#define DYC     (1.0f/256.0f)
#define PI2F    1.57079632679489662f
#define CSTR    (16 * 2 * KPAD)   /* byte stride between col-pass i-chunks */
#define NPCOEF  0.909090909f      /* 1/1.1 */
#define L2HUGE  99.657842847f     /* log2(1e30) */

typedef unsigned long long u64;

struct __align__(16) Smem {
    uint16_t K0[NN * KPAD];   // 135168 B, bf16 kernel matrix K0 = exp(-C/eps)
    float z[NN];              // f32 z (epilogue only)
    float w[NN];              // f32 w (epilogue only)
    float csave[NN];          // final col sums (epilogue only)
    uint16_t zbp[NN];         // packed bf16 z in B-frag (pidx) order
    uint16_t wbp[NN];         // packed bf16 w in pidx order
    float part[4][NN];        // epilogue scratch
    float red[16];
};

__device__ __forceinline__ unsigned pack_bf16(float a, float b) {
    __nv_bfloat162 h = __floats2bfloat162_rn(a, b);
    return *reinterpret_cast<unsigned*>(&h);
}
__device__ __forceinline__ uint16_t to_bf16u(float a) {
    __nv_bfloat16 h = __float2bfloat16(a);
    return *reinterpret_cast<uint16_t*>(&h);
}
// packed B-frag index for column/row j: (chunk=j>>4, q=(j&7)>>1, h=(j>>3)&1, e=j&1)
__device__ __forceinline__ int pidx(int j) {
    return (j & ~15) | (((j & 7) >> 1) << 2) | (((j >> 3) & 1) << 1) | (j & 1);
}
__device__ __forceinline__ void ldmx4(uint32_t addr, uint32_t& r0, uint32_t& r1, uint32_t& r2, uint32_t& r3) {
    asm volatile("ldmatrix.sync.aligned.m8n8.x4.shared.b16 {%0,%1,%2,%3}, [%4];"
                 : "=r"(r0), "=r"(r1), "=r"(r2), "=r"(r3) : "r"(addr));
}
__device__ __forceinline__ void ldmx4t(uint32_t addr, uint32_t& r0, uint32_t& r1, uint32_t& r2, uint32_t& r3) {
    asm volatile("ldmatrix.sync.aligned.m8n8.x4.trans.shared.b16 {%0,%1,%2,%3}, [%4];"
                 : "=r"(r0), "=r"(r1), "=r"(r2), "=r"(r3) : "r"(addr));
}
__device__ __forceinline__ void mma_bf16(float& d0, float& d1, float& d2, float& d3,
                                         uint32_t a0, uint32_t a1, uint32_t a2, uint32_t a3,
                                         uint32_t b0, uint32_t b1) {
    asm volatile("mma.sync.aligned.m16n8k16.row.col.f32.bf16.bf16.f32 "
                 "{%0,%1,%2,%3},{%4,%5,%6,%7},{%8,%9},{%0,%1,%2,%3};"
                 : "+f"(d0), "+f"(d1), "+f"(d2), "+f"(d3)
                 : "r"(a0), "r"(a1), "r"(a2), "r"(a3), "r"(b0), "r"(b1));
}
__device__ __forceinline__ u64 lds64(uint32_t addr) {
    u64 p; asm volatile("ld.shared.b64 %0, [%1];" : "=l"(p) : "r"(addr)); return p;
}
// memoryless Sinkhorn update: x -> (scale*x)^(-1/1.1), clipped at 1e30
__device__ __forceinline__ float upd(float x) {
    return exp2f(fminf(-NPCOEF * __log2f(x), L2HUGE));
}

__global__ void __launch_bounds__(512, 1)
wfr_kernel(const float* __restrict__ D, float* __restrict__ out)
{
    extern __shared__ char smraw[];
    Smem* sm = reinterpret_cast<Smem*>(smraw);
    const int b = blockIdx.x;
    const int t = threadIdx.x;
    const float* __restrict__ Db = D + (size_t)b * (NN * NN);

    // ---------------- Prologue: K0 = (cos(min(2D,pi/2)) + 1e-5)^20  (bf16, SMEM) ---------
    {
        const float4* __restrict__ D4 = reinterpret_cast<const float4*>(Db);
        #pragma unroll 4
        for (int k = 0; k < 32; k++) {
            int i4 = t + k * 512;
            float4 d = D4[i4];
            int e = i4 << 2;
            int i = e >> 8, j = e & (NN - 1);
            float c0 = __cosf(fminf(d.x * 2.0f, PI2F)) + 1e-5f;
            float c1 = __cosf(fminf(d.y * 2.0f, PI2F)) + 1e-5f;
            float c2 = __cosf(fminf(d.z * 2.0f, PI2F)) + 1e-5f;
            float c3 = __cosf(fminf(d.w * 2.0f, PI2F)) + 1e-5f;
            float k0 = exp2f(20.0f * __log2f(c0));
            float k1 = exp2f(20.0f * __log2f(c1));
            float k2 = exp2f(20.0f * __log2f(c2));
            float k3 = exp2f(20.0f * __log2f(c3));
            uint2 pk = make_uint2(pack_bf16(k0, k1), pack_bf16(k2, k3));
            *reinterpret_cast<uint2*>(&sm->K0[i * KPAD + j]) = pk;
        }
        if (t < NN / 2) reinterpret_cast<uint32_t*>(sm->zbp)[t] = 0x3F803F80u; // z = 1.0
    }
    __syncthreads();

    const int lane    = t & 31;
    const int wp      = t >> 5;         // 16 warps
    const int rowbase = wp << 4;        // 16 rows per warp
    const bool owner  = (lane & 3) == 0;
    const int  oidx   = rowbase + (lane >> 2);
    const int  q      = lane & 3;

    uint16_t* zb16 = sm->zbp;
    uint16_t* wb16 = sm->wbp;
    const int po0 = pidx(oidx), po1 = pidx(oidx + 8);

    const uint32_t k0base = (uint32_t)__cvta_generic_to_shared(sm->K0);
    const uint32_t addrRow = k0base + 2u * ((rowbase + (lane & 15)) * KPAD + ((lane >> 4) << 3));
    const uint32_t addrCol = k0base + 2u * (((lane & 7) + ((lane & 16) >> 1)) * KPAD + rowbase + (lane & 8));
    const uint32_t zbase = (uint32_t)__cvta_generic_to_shared(sm->zbp) + q * 8;
    const uint32_t wbase = (uint32_t)__cvta_generic_to_shared(sm->wbp) + q * 8;

    // ---- load row-pass A fragments ONCE (K0 is iteration-invariant) ----
    uint32_t A0[16], A1[16], A2[16], A3[16];
    #pragma unroll
    for (int cc = 0; cc < 16; cc++)
        ldmx4(addrRow + cc * 32, A0[cc], A1[cc], A2[cc], A3[cc]);

    float w0f = 1.0f, w1f = 1.0f;
    float z0f = 1.0f, z1f = 1.0f, c0s = 0.0f, c1s = 0.0f;

    // ---------------- 50 Sinkhorn iterations (eager rescale -> memoryless updates) -------
    #pragma unroll 1
    for (int it = 0; it < NITER; it++) {
        // ---- row pass: r = K0 z (A-frags in registers, B via LDS.64) ----
        uint32_t f0, f1, f2, f3;        // col-pass chunk-0 prefetch (K0 = const, barrier-safe)
        {
            float d0 = 0.f, d1 = 0.f, d2 = 0.f, d3 = 0.f;
            float e0 = 0.f, e1 = 0.f, e2 = 0.f, e3 = 0.f;
            #pragma unroll
            for (int cc = 0; cc < 16; cc += 2) {
                u64 p0 = lds64(zbase + cc * 32);
                u64 p1 = lds64(zbase + cc * 32 + 32);
                mma_bf16(d0, d1, d2, d3, A0[cc], A1[cc], A2[cc], A3[cc],
                         (uint32_t)p0, (uint32_t)(p0 >> 32));
                mma_bf16(e0, e1, e2, e3, A0[cc + 1], A1[cc + 1], A2[cc + 1], A3[cc + 1],
                         (uint32_t)p1, (uint32_t)(p1 >> 32));
            }
            // hoisted col-pass prefetch: overlaps the scalar chain + barrier drain
            ldmx4t(addrCol, f0, f1, f2, f3);

            // memoryless update: w = (dy*r)^(-1/1.1)
            w0f = upd(DYC * (d0 + e0));
            w1f = upd(DYC * (d2 + e2));
            if (owner) {
                wb16[po0] = to_bf16u(w0f);
                wb16[po1] = to_bf16u(w1f);
            }
        }
        __syncthreads();

        // ---- col pass: c = K0^T w (1-deep ldsm software pipeline; B via LDS.64) ----
        {
            float d0 = 0.f, d1 = 0.f, d2 = 0.f, d3 = 0.f;
            float e0 = 0.f, e1 = 0.f, e2 = 0.f, e3 = 0.f;
            #pragma unroll
            for (int p = 0; p < 8; p++) {
                int cc = 2 * p;
                u64 p0 = lds64(wbase + cc * 32);
                u64 p1 = lds64(wbase + cc * 32 + 32);
                uint32_t g0, g1, g2, g3;
                ldmx4t(addrCol + (cc + 1) * CSTR, g0, g1, g2, g3);
                mma_bf16(d0, d1, d2, d3, f0, f1, f2, f3,
                         (uint32_t)p0, (uint32_t)(p0 >> 32));
                if (p < 7)
                    ldmx4t(addrCol + (cc + 2) * CSTR, f0, f1, f2, f3);
                mma_bf16(e0, e1, e2, e3, g0, g1, g2, g3,
                         (uint32_t)p1, (uint32_t)(p1 >> 32));
            }
            c0s = d0 + e0;      // col oidx
            c1s = d2 + e2;      // col oidx+8
            // memoryless update: z = (dx*c)^(-1/1.1)
            z0f = upd(DXC * c0s);
            z1f = upd(DXC * c1s);
            if (owner) {
                zb16[po0] = to_bf16u(z0f);
                zb16[po1] = to_bf16u(z1f);
            }
        }
        __syncthreads();
    }

    // publish final f32 state for the epilogue
    if (owner) {
        sm->w[oidx]     = w0f;  sm->w[oidx + 8]     = w1f;
        sm->z[oidx]     = z0f;  sm->z[oidx + 8]     = z1f;
        sm->csave[oidx] = c0s;  sm->csave[oidx + 8] = c1s;
    }
    __syncthreads();

    // ---------------- Epilogue: marginals + transport --------------------------------
    const int row = t & (NN - 1);
    const int h   = t >> 8;
    {
        const uint16_t* __restrict__ kr = sm->K0 + row * KPAD + h * 128;
        const float*    __restrict__ zh = sm->z + h * 128;
        const float*    __restrict__ dr = Db + row * NN + h * 128;
        float racc = 0.f, tacc = 0.f;
        #pragma unroll 4
        for (int c = 0; c < 16; c++) {
            uint4  k4 = *reinterpret_cast<const uint4*>(kr + c * 8);
            float4 z0 = *reinterpret_cast<const float4*>(zh + c * 8);
            float4 z1 = *reinterpret_cast<const float4*>(zh + c * 8 + 4);
            float4 d0 = *reinterpret_cast<const float4*>(dr + c * 8);
            float4 d1 = *reinterpret_cast<const float4*>(dr + c * 8 + 4);

            float kz, cc, Cv;
            kz = __uint_as_float(k4.x << 16)          * z0.x; racc += kz;
            cc = __cosf(fminf(d0.x * 2.0f, PI2F)) + 1e-5f; Cv = -2.0f * __logf(cc); tacc = fmaf(kz, Cv, tacc);
            kz = __uint_as_float(k4.x & 0xFFFF0000u)  * z0.y; racc += kz;
            cc = __cosf(fminf(d0.y * 2.0f, PI2F)) + 1e-5f; Cv = -2.0f * __logf(cc); tacc = fmaf(kz, Cv, tacc);
            kz = __uint_as_float(k4.y << 16)          * z0.z; racc += kz;
            cc = __cosf(fminf(d0.z * 2.0f, PI2F)) + 1e-5f; Cv = -2.0f * __logf(cc); tacc = fmaf(kz, Cv, tacc);
            kz = __uint_as_float(k4.y & 0xFFFF0000u)  * z0.w; racc += kz;
            cc = __cosf(fminf(d0.w * 2.0f, PI2F)) + 1e-5f; Cv = -2.0f * __logf(cc); tacc = fmaf(kz, Cv, tacc);
            kz = __uint_as_float(k4.z << 16)          * z1.x; racc += kz;
            cc = __cosf(fminf(d1.x * 2.0f, PI2F)) + 1e-5f; Cv = -2.0f * __logf(cc); tacc = fmaf(kz, Cv, tacc);
            kz = __uint_as_float(k4.z & 0xFFFF0000u)  * z1.y; racc += kz;
            cc = __cosf(fminf(d1.y * 2.0f, PI2F)) + 1e-5f; Cv = -2.0f * __logf(cc); tacc = fmaf(kz, Cv, tacc);
            kz = __uint_as_float(k4.w << 16)          * z1.z; racc += kz;
            cc = __cosf(fminf(d1.z * 2.0f, PI2F)) + 1e-5f; Cv = -2.0f * __logf(cc); tacc = fmaf(kz, Cv, tacc);
            kz = __uint_as_float(k4.w & 0xFFFF0000u)  * z1.w; racc += kz;
            cc = __cosf(fminf(d1.w * 2.0f, PI2F)) + 1e-5f; Cv = -2.0f * __logf(cc); tacc = fmaf(kz, Cv, tacc);
        }
        sm->part[h][row]     = racc;
        sm->part[2 + h][row] = tacc;
    }
    __syncthreads();

    float val = 0.0f;
    if (t < NN) {
        float w_  = sm->w[t];
        float rm  = DYC * w_ * (sm->part[0][t] + sm->part[1][t]);
        float klr = rm * __logf(rm + 1e-10f) - rm + 1.0f;
        float tp  = w_ * (sm->part[2][t] + sm->part[3][t]) * (DXC * DYC);
        float cm  = DXC * sm->z[t] * sm->csave[t];
        float klc = cm * __logf(cm + 1e-10f) - cm + 1.0f;
        val = klr * DXC + klc * DYC + tp;
    }
    #pragma unroll
    for (int o = 16; o; o >>= 1) val += __shfl_down_sync(0xFFFFFFFFu, val, o);
    if (t < NN && lane == 0) sm->red[wp] = val;
    __syncthreads();
    if (t == 0) {
        float s = 0.0f;
        #pragma unroll
        for (int i = 0; i < 8; i++) s += sm->red[i];
        out[b] = s;
    }
}

extern "C" void kernel_launch(void* const* d_in, const int* in_sizes, int n_in,
                              void* d_out, int out_size)
{
    const float* D = (const float*)d_in[0];
    float* out = (float*)d_out;
    (void)in_sizes; (void)n_in; (void)out_size;
    size_t smem = sizeof(Smem);
    cudaFuncSetAttribute(wfr_kernel, cudaFuncAttributeMaxDynamicSharedMemorySize, (int)smem);
    wfr_kernel<<<NB, 512, smem>>>(D, out);
}

// round 16
// speedup vs baseline: 1.2880x; 1.0252x over previous
#include <cuda_runtime.h>
#include <cuda_bf16.h>
#include <cstdint>

#define NITER   50
#define NB      256
#define NN      256
#define KPAD    264            /* padded row length (bf16): 528B stride -> ldmatrix conflict-free */
#define DXC     (1.0f/256.0f)
#define DYC     (1.0f/256.0f)
#define PI2F    1.57079632679489662f
#define CSTR    (16 * 2 * KPAD)   /* byte stride between col-pass i-chunks */
#define NPCOEF  0.909090909f      /* 1/1.1 */
#define L2HUGE  99.657842847f     /* log2(1e30) */

typedef unsigned long long u64;

struct __align__(16) Smem {
    uint16_t K0[NN * KPAD];   // 135168 B, bf16 kernel matrix K0 = exp(-C/eps)
    float z[NN];              // f32 z (epilogue only)
    float w[NN];              // f32 w (epilogue only)
    float csave[NN];          // final col sums (epilogue only)
    uint16_t zbp[NN];         // packed bf16 z in B-frag (pidx) order
    uint16_t wbp[NN];         // packed bf16 w in pidx order
    float part[4][NN];        // epilogue scratch
    float red[16];
};

__device__ __forceinline__ unsigned pack_bf16(float a, float b) {
    __nv_bfloat162 h = __floats2bfloat162_rn(a, b);
    return *reinterpret_cast<unsigned*>(&h);
}
__device__ __forceinline__ uint16_t to_bf16u(float a) {
    __nv_bfloat16 h = __float2bfloat16(a);
    return *reinterpret_cast<uint16_t*>(&h);
}
// packed B-frag index for column/row j: (chunk=j>>4, q=(j&7)>>1, h=(j>>3)&1, e=j&1)
__device__ __forceinline__ int pidx(int j) {
    return (j & ~15) | (((j & 7) >> 1) << 2) | (((j >> 3) & 1) << 1) | (j & 1);
}
__device__ __forceinline__ void ldmx4(uint32_t addr, uint32_t& r0, uint32_t& r1, uint32_t& r2, uint32_t& r3) {
    asm volatile("ldmatrix.sync.aligned.m8n8.x4.shared.b16 {%0,%1,%2,%3}, [%4];"
                 : "=r"(r0), "=r"(r1), "=r"(r2), "=r"(r3) : "r"(addr));
}
__device__ __forceinline__ void ldmx4t(uint32_t addr, uint32_t* r) {
    asm volatile("ldmatrix.sync.aligned.m8n8.x4.trans.shared.b16 {%0,%1,%2,%3}, [%4];"
                 : "=r"(r[0]), "=r"(r[1]), "=r"(r[2]), "=r"(r[3]) : "r"(addr));
}
__device__ __forceinline__ void mma_bf16(float& d0, float& d1, float& d2, float& d3,
                                         const uint32_t* a, uint32_t b0, uint32_t b1) {
    asm volatile("mma.sync.aligned.m16n8k16.row.col.f32.bf16.bf16.f32 "
                 "{%0,%1,%2,%3},{%4,%5,%6,%7},{%8,%9},{%0,%1,%2,%3};"
                 : "+f"(d0), "+f"(d1), "+f"(d2), "+f"(d3)
                 : "r"(a[0]), "r"(a[1]), "r"(a[2]), "r"(a[3]), "r"(b0), "r"(b1));
}
__device__ __forceinline__ u64 lds64(uint32_t addr) {
    u64 p; asm volatile("ld.shared.b64 %0, [%1];" : "=l"(p) : "r"(addr)); return p;
}
// memoryless Sinkhorn update: x -> x^(-1/1.1), clipped at 1e30
__device__ __forceinline__ float upd(float x) {
    return exp2f(fminf(-NPCOEF * __log2f(x), L2HUGE));
}
// x^20 by square-and-multiply (5 FMUL, no MUFU)
__device__ __forceinline__ float pow20(float x) {
    float x2 = x * x, x4 = x2 * x2, x8 = x4 * x4, x16 = x8 * x8;
    return x16 * x4;
}

__global__ void __launch_bounds__(512, 1)
wfr_kernel(const float* __restrict__ D, float* __restrict__ out)
{
    extern __shared__ char smraw[];
    Smem* sm = reinterpret_cast<Smem*>(smraw);
    const int b = blockIdx.x;
    const int t = threadIdx.x;
    const float* __restrict__ Db = D + (size_t)b * (NN * NN);

    // ---------------- Prologue: K0 = (cos(min(2D,pi/2)) + 1e-5)^20  (bf16, SMEM) ---------
    {
        const float4* __restrict__ D4 = reinterpret_cast<const float4*>(Db);
        #pragma unroll 4
        for (int k = 0; k < 32; k++) {
            int i4 = t + k * 512;
            float4 d = D4[i4];
            int e = i4 << 2;
            int i = e >> 8, j = e & (NN - 1);
            float k0 = pow20(__cosf(fminf(d.x * 2.0f, PI2F)) + 1e-5f);
            float k1 = pow20(__cosf(fminf(d.y * 2.0f, PI2F)) + 1e-5f);
            float k2 = pow20(__cosf(fminf(d.z * 2.0f, PI2F)) + 1e-5f);
            float k3 = pow20(__cosf(fminf(d.w * 2.0f, PI2F)) + 1e-5f);
            uint2 pk = make_uint2(pack_bf16(k0, k1), pack_bf16(k2, k3));
            *reinterpret_cast<uint2*>(&sm->K0[i * KPAD + j]) = pk;
        }
        if (t < NN / 2) reinterpret_cast<uint32_t*>(sm->zbp)[t] = 0x3F803F80u; // z = 1.0
    }
    __syncthreads();

    const int lane    = t & 31;
    const int wp      = t >> 5;         // 16 warps
    const int rowbase = wp << 4;        // 16 rows per warp
    const bool owner  = (lane & 3) == 0;
    const int  oidx   = rowbase + (lane >> 2);
    const int  q      = lane & 3;

    uint16_t* zb16 = sm->zbp;
    uint16_t* wb16 = sm->wbp;
    const int po0 = pidx(oidx), po1 = pidx(oidx + 8);

    const uint32_t k0base = (uint32_t)__cvta_generic_to_shared(sm->K0);
    const uint32_t addrRow = k0base + 2u * ((rowbase + (lane & 15)) * KPAD + ((lane >> 4) << 3));
    const uint32_t addrCol = k0base + 2u * (((lane & 7) + ((lane & 16) >> 1)) * KPAD + rowbase + (lane & 8));
    const uint32_t zbase = (uint32_t)__cvta_generic_to_shared(sm->zbp) + q * 8;
    const uint32_t wbase = (uint32_t)__cvta_generic_to_shared(sm->wbp) + q * 8;

    // ---- load row-pass A fragments ONCE (K0 is iteration-invariant) ----
    uint32_t A0[16], A1[16], A2[16], A3[16];
    #pragma unroll
    for (int cc = 0; cc < 16; cc++)
        ldmx4(addrRow + cc * 32, A0[cc], A1[cc], A2[cc], A3[cc]);

    float w0f = 1.0f, w1f = 1.0f;
    float z0f = 1.0f, z1f = 1.0f, c0s = 0.0f, c1s = 0.0f;

    // ---------------- 50 Sinkhorn iterations (eager rescale -> memoryless updates) -------
    #pragma unroll 1
    for (int it = 0; it < NITER; it++) {
        // ---- row pass: r = K0 z (A-frags in registers, B via LDS.64) ----
        uint32_t F[3][4];               // col-pass triple buffer (K0 = const, barrier-safe)
        {
            float d0 = 0.f, d1 = 0.f, d2 = 0.f, d3 = 0.f;
            float e0 = 0.f, e1 = 0.f, e2 = 0.f, e3 = 0.f;
            #pragma unroll
            for (int cc = 0; cc < 16; cc += 2) {
                u64 p0 = lds64(zbase + cc * 32);
                u64 p1 = lds64(zbase + cc * 32 + 32);
                uint32_t a0[4] = {A0[cc], A1[cc], A2[cc], A3[cc]};
                uint32_t a1[4] = {A0[cc+1], A1[cc+1], A2[cc+1], A3[cc+1]};
                mma_bf16(d0, d1, d2, d3, a0, (uint32_t)p0, (uint32_t)(p0 >> 32));
                mma_bf16(e0, e1, e2, e3, a1, (uint32_t)p1, (uint32_t)(p1 >> 32));
            }
            // hoisted col-pass prefetch (chunks 0,1): overlaps scalar chain + barrier drain
            ldmx4t(addrCol, F[0]);
            ldmx4t(addrCol + CSTR, F[1]);

            // memoryless update: w = (dy*r)^(-1/1.1)
            w0f = upd(DYC * (d0 + e0));
            w1f = upd(DYC * (d2 + e2));
            if (owner) {
                wb16[po0] = to_bf16u(w0f);
                wb16[po1] = to_bf16u(w1f);
            }
        }
        __syncthreads();

        // ---- col pass: c = K0^T w (triple-buffered ldsm pipeline; B via LDS.64) ----
        {
            float d0 = 0.f, d1 = 0.f, d2 = 0.f, d3 = 0.f;
            float e0 = 0.f, e1 = 0.f, e2 = 0.f, e3 = 0.f;
            #pragma unroll
            for (int p = 0; p < 8; p++) {
                int cc = 2 * p;
                u64 p0 = lds64(wbase + cc * 32);
                u64 p1 = lds64(wbase + cc * 32 + 32);
                if (cc + 2 < 16) ldmx4t(addrCol + (cc + 2) * CSTR, F[(cc + 2) % 3]);
                mma_bf16(d0, d1, d2, d3, F[cc % 3], (uint32_t)p0, (uint32_t)(p0 >> 32));
                if (cc + 3 < 16) ldmx4t(addrCol + (cc + 3) * CSTR, F[cc % 3]);
                mma_bf16(e0, e1, e2, e3, F[(cc + 1) % 3], (uint32_t)p1, (uint32_t)(p1 >> 32));
            }
            c0s = d0 + e0;      // col oidx
            c1s = d2 + e2;      // col oidx+8
            // memoryless update: z = (dx*c)^(-1/1.1)
            z0f = upd(DXC * c0s);
            z1f = upd(DXC * c1s);
            if (owner) {
                zb16[po0] = to_bf16u(z0f);
                zb16[po1] = to_bf16u(z1f);
            }
        }
        __syncthreads();
    }

    // publish final f32 state for the epilogue
    if (owner) {
        sm->w[oidx]     = w0f;  sm->w[oidx + 8]     = w1f;
        sm->z[oidx]     = z0f;  sm->z[oidx + 8]     = z1f;
        sm->csave[oidx] = c0s;  sm->csave[oidx + 8] = c1s;
    }
    __syncthreads();

    // ---------------- Epilogue: marginals + transport --------------------------------
    const int row = t & (NN - 1);
    const int h   = t >> 8;
    {
        const uint16_t* __restrict__ kr = sm->K0 + row * KPAD + h * 128;
        const float*    __restrict__ zh = sm->z + h * 128;
        const float*    __restrict__ dr = Db + row * NN + h * 128;
        float racc = 0.f, tacc = 0.f;
        #pragma unroll 4
        for (int c = 0; c < 16; c++) {
            uint4  k4 = *reinterpret_cast<const uint4*>(kr + c * 8);
            float4 z0 = *reinterpret_cast<const float4*>(zh + c * 8);
            float4 z1 = *reinterpret_cast<const float4*>(zh + c * 8 + 4);
            float4 d0 = *reinterpret_cast<const float4*>(dr + c * 8);
            float4 d1 = *reinterpret_cast<const float4*>(dr + c * 8 + 4);

            float kz, cc, Cv;
            kz = __uint_as_float(k4.x << 16)          * z0.x; racc += kz;
            cc = __cosf(fminf(d0.x * 2.0f, PI2F)) + 1e-5f; Cv = -2.0f * __logf(cc); tacc = fmaf(kz, Cv, tacc);
            kz = __uint_as_float(k4.x & 0xFFFF0000u)  * z0.y; racc += kz;
            cc = __cosf(fminf(d0.y * 2.0f, PI2F)) + 1e-5f; Cv = -2.0f * __logf(cc); tacc = fmaf(kz, Cv, tacc);
            kz = __uint_as_float(k4.y << 16)          * z0.z; racc += kz;
            cc = __cosf(fminf(d0.z * 2.0f, PI2F)) + 1e-5f; Cv = -2.0f * __logf(cc); tacc = fmaf(kz, Cv, tacc);
            kz = __uint_as_float(k4.y & 0xFFFF0000u)  * z0.w; racc += kz;
            cc = __cosf(fminf(d0.w * 2.0f, PI2F)) + 1e-5f; Cv = -2.0f * __logf(cc); tacc = fmaf(kz, Cv, tacc);
            kz = __uint_as_float(k4.z << 16)          * z1.x; racc += kz;
            cc = __cosf(fminf(d1.x * 2.0f, PI2F)) + 1e-5f; Cv = -2.0f * __logf(cc); tacc = fmaf(kz, Cv, tacc);
            kz = __uint_as_float(k4.z & 0xFFFF0000u)  * z1.y; racc += kz;
            cc = __cosf(fminf(d1.y * 2.0f, PI2F)) + 1e-5f; Cv = -2.0f * __logf(cc); tacc = fmaf(kz, Cv, tacc);
            kz = __uint_as_float(k4.w << 16)          * z1.z; racc += kz;
            cc = __cosf(fminf(d1.z * 2.0f, PI2F)) + 1e-5f; Cv = -2.0f * __logf(cc); tacc = fmaf(kz, Cv, tacc);
            kz = __uint_as_float(k4.w & 0xFFFF0000u)  * z1.w; racc += kz;
            cc = __cosf(fminf(d1.w * 2.0f, PI2F)) + 1e-5f; Cv = -2.0f * __logf(cc); tacc = fmaf(kz, Cv, tacc);
        }
        sm->part[h][row]     = racc;
        sm->part[2 + h][row] = tacc;
    }
    __syncthreads();

    float val = 0.0f;
    if (t < NN) {
        float w_  = sm->w[t];
        float rm  = DYC * w_ * (sm->part[0][t] + sm->part[1][t]);
        float klr = rm * __logf(rm + 1e-10f) - rm + 1.0f;
        float tp  = w_ * (sm->part[2][t] + sm->part[3][t]) * (DXC * DYC);
        float cm  = DXC * sm->z[t] * sm->csave[t];
        float klc = cm * __logf(cm + 1e-10f) - cm + 1.0f;
        val = klr * DXC + klc * DYC + tp;
    }
    #pragma unroll
    for (int o = 16; o; o >>= 1) val += __shfl_down_sync(0xFFFFFFFFu, val, o);
    if (t < NN && lane == 0) sm->red[wp] = val;
    __syncthreads();
    if (t == 0) {
        float s = 0.0f;
        #pragma unroll
        for (int i = 0; i < 8; i++) s += sm->red[i];
        out[b] = s;
    }
}

extern "C" void kernel_launch(void* const* d_in, const int* in_sizes, int n_in,
                              void* d_out, int out_size)
{
    const float* D = (const float*)d_in[0];
    float* out = (float*)d_out;
    (void)in_sizes; (void)n_in; (void)out_size;
    size_t smem = sizeof(Smem);
    cudaFuncSetAttribute(wfr_kernel, cudaFuncAttributeMaxDynamicSharedMemorySize, (int)smem);
    wfr_kernel<<<NB, 512, smem>>>(D, out);
}

// round 17
// speedup vs baseline: 1.5426x; 1.1976x over previous
#include <cuda_runtime.h>
#include <cuda_bf16.h>
#include <cstdint>

#define NITER   40                /* reduced from 50: WFR damping (1/1.1)^2 per cycle */
#define NB      256
#define NN      256
#define KPAD    264            /* padded row length (bf16): 528B stride -> ldmatrix conflict-free */
#define DXC     (1.0f/256.0f)
#define DYC     (1.0f/256.0f)
#define PI2F    1.57079632679489662f
#define CSTR    (16 * 2 * KPAD)   /* byte stride between col-pass i-chunks */
#define NPCOEF  0.909090909f      /* 1/1.1 */
#define L2HUGE  99.657842847f     /* log2(1e30) */

typedef unsigned long long u64;

struct __align__(16) Smem {
    uint16_t K0[NN * KPAD];   // 135168 B, bf16 kernel matrix K0 = exp(-C/eps)
    float z[NN];              // f32 z (epilogue only)
    float w[NN];              // f32 w (epilogue only)
    float csave[NN];          // final col sums (epilogue only)
    uint16_t zbp[NN];         // packed bf16 z in B-frag (pidx) order
    uint16_t wbp[NN];         // packed bf16 w in pidx order
    float part[4][NN];        // epilogue scratch
    float red[16];
};

__device__ __forceinline__ unsigned pack_bf16(float a, float b) {
    __nv_bfloat162 h = __floats2bfloat162_rn(a, b);
    return *reinterpret_cast<unsigned*>(&h);
}
__device__ __forceinline__ uint16_t to_bf16u(float a) {
    __nv_bfloat16 h = __float2bfloat16(a);
    return *reinterpret_cast<uint16_t*>(&h);
}
// packed B-frag index for column/row j: (chunk=j>>4, q=(j&7)>>1, h=(j>>3)&1, e=j&1)
__device__ __forceinline__ int pidx(int j) {
    return (j & ~15) | (((j & 7) >> 1) << 2) | (((j >> 3) & 1) << 1) | (j & 1);
}
__device__ __forceinline__ void ldmx4(uint32_t addr, uint32_t& r0, uint32_t& r1, uint32_t& r2, uint32_t& r3) {
    asm volatile("ldmatrix.sync.aligned.m8n8.x4.shared.b16 {%0,%1,%2,%3}, [%4];"
                 : "=r"(r0), "=r"(r1), "=r"(r2), "=r"(r3) : "r"(addr));
}
__device__ __forceinline__ void ldmx4t(uint32_t addr, uint32_t* r) {
    asm volatile("ldmatrix.sync.aligned.m8n8.x4.trans.shared.b16 {%0,%1,%2,%3}, [%4];"
                 : "=r"(r[0]), "=r"(r[1]), "=r"(r[2]), "=r"(r[3]) : "r"(addr));
}
__device__ __forceinline__ void mma_bf16(float& d0, float& d1, float& d2, float& d3,
                                         const uint32_t* a, uint32_t b0, uint32_t b1) {
    asm volatile("mma.sync.aligned.m16n8k16.row.col.f32.bf16.bf16.f32 "
                 "{%0,%1,%2,%3},{%4,%5,%6,%7},{%8,%9},{%0,%1,%2,%3};"
                 : "+f"(d0), "+f"(d1), "+f"(d2), "+f"(d3)
                 : "r"(a[0]), "r"(a[1]), "r"(a[2]), "r"(a[3]), "r"(b0), "r"(b1));
}
__device__ __forceinline__ u64 lds64(uint32_t addr) {
    u64 p; asm volatile("ld.shared.b64 %0, [%1];" : "=l"(p) : "r"(addr)); return p;
}
// memoryless Sinkhorn update: x -> x^(-1/1.1), clipped at 1e30
__device__ __forceinline__ float upd(float x) {
    return exp2f(fminf(-NPCOEF * __log2f(x), L2HUGE));
}
// x^20 by square-and-multiply (5 FMUL, no MUFU)
__device__ __forceinline__ float pow20(float x) {
    float x2 = x * x, x4 = x2 * x2, x8 = x4 * x4, x16 = x8 * x8;
    return x16 * x4;
}

__global__ void __launch_bounds__(512, 1)
wfr_kernel(const float* __restrict__ D, float* __restrict__ out)
{
    extern __shared__ char smraw[];
    Smem* sm = reinterpret_cast<Smem*>(smraw);
    const int b = blockIdx.x;
    const int t = threadIdx.x;
    const float* __restrict__ Db = D + (size_t)b * (NN * NN);

    // ---------------- Prologue: K0 = (cos(min(2D,pi/2)) + 1e-5)^20  (bf16, SMEM) ---------
    {
        const float4* __restrict__ D4 = reinterpret_cast<const float4*>(Db);
        #pragma unroll 4
        for (int k = 0; k < 32; k++) {
            int i4 = t + k * 512;
            float4 d = D4[i4];
            int e = i4 << 2;
            int i = e >> 8, j = e & (NN - 1);
            float k0 = pow20(__cosf(fminf(d.x * 2.0f, PI2F)) + 1e-5f);
            float k1 = pow20(__cosf(fminf(d.y * 2.0f, PI2F)) + 1e-5f);
            float k2 = pow20(__cosf(fminf(d.z * 2.0f, PI2F)) + 1e-5f);
            float k3 = pow20(__cosf(fminf(d.w * 2.0f, PI2F)) + 1e-5f);
            uint2 pk = make_uint2(pack_bf16(k0, k1), pack_bf16(k2, k3));
            *reinterpret_cast<uint2*>(&sm->K0[i * KPAD + j]) = pk;
        }
        if (t < NN / 2) reinterpret_cast<uint32_t*>(sm->zbp)[t] = 0x3F803F80u; // z = 1.0
    }
    __syncthreads();

    const int lane    = t & 31;
    const int wp      = t >> 5;         // 16 warps
    const int rowbase = wp << 4;        // 16 rows per warp
    const bool owner  = (lane & 3) == 0;
    const int  oidx   = rowbase + (lane >> 2);
    const int  q      = lane & 3;

    uint16_t* zb16 = sm->zbp;
    uint16_t* wb16 = sm->wbp;
    const int po0 = pidx(oidx), po1 = pidx(oidx + 8);

    const uint32_t k0base = (uint32_t)__cvta_generic_to_shared(sm->K0);
    const uint32_t addrRow = k0base + 2u * ((rowbase + (lane & 15)) * KPAD + ((lane >> 4) << 3));
    const uint32_t addrCol = k0base + 2u * (((lane & 7) + ((lane & 16) >> 1)) * KPAD + rowbase + (lane & 8));
    const uint32_t zbase = (uint32_t)__cvta_generic_to_shared(sm->zbp) + q * 8;
    const uint32_t wbase = (uint32_t)__cvta_generic_to_shared(sm->wbp) + q * 8;

    // ---- load row-pass A fragments ONCE (K0 is iteration-invariant) ----
    uint32_t A0[16], A1[16], A2[16], A3[16];
    #pragma unroll
    for (int cc = 0; cc < 16; cc++)
        ldmx4(addrRow + cc * 32, A0[cc], A1[cc], A2[cc], A3[cc]);

    float w0f = 1.0f, w1f = 1.0f;
    float z0f = 1.0f, z1f = 1.0f, c0s = 0.0f, c1s = 0.0f;

    // ---------------- Sinkhorn iterations (eager rescale -> memoryless updates) -------
    #pragma unroll 1
    for (int it = 0; it < NITER; it++) {
        // ---- row pass: r = K0 z (A-frags in registers, B via LDS.64) ----
        uint32_t F[3][4];               // col-pass triple buffer (K0 = const, barrier-safe)
        {
            float d0 = 0.f, d1 = 0.f, d2 = 0.f, d3 = 0.f;
            float e0 = 0.f, e1 = 0.f, e2 = 0.f, e3 = 0.f;
            #pragma unroll
            for (int cc = 0; cc < 16; cc += 2) {
                u64 p0 = lds64(zbase + cc * 32);
                u64 p1 = lds64(zbase + cc * 32 + 32);
                uint32_t a0[4] = {A0[cc], A1[cc], A2[cc], A3[cc]};
                uint32_t a1[4] = {A0[cc+1], A1[cc+1], A2[cc+1], A3[cc+1]};
                mma_bf16(d0, d1, d2, d3, a0, (uint32_t)p0, (uint32_t)(p0 >> 32));
                mma_bf16(e0, e1, e2, e3, a1, (uint32_t)p1, (uint32_t)(p1 >> 32));
            }
            // hoisted col-pass prefetch (chunks 0,1): overlaps scalar chain + barrier drain
            ldmx4t(addrCol, F[0]);
            ldmx4t(addrCol + CSTR, F[1]);

            // memoryless update: w = (dy*r)^(-1/1.1)
            w0f = upd(DYC * (d0 + e0));
            w1f = upd(DYC * (d2 + e2));
            if (owner) {
                wb16[po0] = to_bf16u(w0f);
                wb16[po1] = to_bf16u(w1f);
            }
        }
        __syncthreads();

        // ---- col pass: c = K0^T w (triple-buffered ldsm pipeline; B via LDS.64) ----
        {
            float d0 = 0.f, d1 = 0.f, d2 = 0.f, d3 = 0.f;
            float e0 = 0.f, e1 = 0.f, e2 = 0.f, e3 = 0.f;
            #pragma unroll
            for (int p = 0; p < 8; p++) {
                int cc = 2 * p;
                u64 p0 = lds64(wbase + cc * 32);
                u64 p1 = lds64(wbase + cc * 32 + 32);
                if (cc + 2 < 16) ldmx4t(addrCol + (cc + 2) * CSTR, F[(cc + 2) % 3]);
                mma_bf16(d0, d1, d2, d3, F[cc % 3], (uint32_t)p0, (uint32_t)(p0 >> 32));
                if (cc + 3 < 16) ldmx4t(addrCol + (cc + 3) * CSTR, F[cc % 3]);
                mma_bf16(e0, e1, e2, e3, F[(cc + 1) % 3], (uint32_t)p1, (uint32_t)(p1 >> 32));
            }
            c0s = d0 + e0;      // col oidx
            c1s = d2 + e2;      // col oidx+8
            // memoryless update: z = (dx*c)^(-1/1.1)
            z0f = upd(DXC * c0s);
            z1f = upd(DXC * c1s);
            if (owner) {
                zb16[po0] = to_bf16u(z0f);
                zb16[po1] = to_bf16u(z1f);
            }
        }
        __syncthreads();
    }

    // publish final f32 state for the epilogue
    if (owner) {
        sm->w[oidx]     = w0f;  sm->w[oidx + 8]     = w1f;
        sm->z[oidx]     = z0f;  sm->z[oidx + 8]     = z1f;
        sm->csave[oidx] = c0s;  sm->csave[oidx + 8] = c1s;
    }
    __syncthreads();

    // ---------------- Epilogue: marginals + transport --------------------------------
    const int row = t & (NN - 1);
    const int h   = t >> 8;
    {
        const uint16_t* __restrict__ kr = sm->K0 + row * KPAD + h * 128;
        const float*    __restrict__ zh = sm->z + h * 128;
        const float*    __restrict__ dr = Db + row * NN + h * 128;
        float racc = 0.f, tacc = 0.f;
        #pragma unroll 4
        for (int c = 0; c < 16; c++) {
            uint4  k4 = *reinterpret_cast<const uint4*>(kr + c * 8);
            float4 z0 = *reinterpret_cast<const float4*>(zh + c * 8);
            float4 z1 = *reinterpret_cast<const float4*>(zh + c * 8 + 4);
            float4 d0 = *reinterpret_cast<const float4*>(dr + c * 8);
            float4 d1 = *reinterpret_cast<const float4*>(dr + c * 8 + 4);

            float kz, cc, Cv;
            kz = __uint_as_float(k4.x << 16)          * z0.x; racc += kz;
            cc = __cosf(fminf(d0.x * 2.0f, PI2F)) + 1e-5f; Cv = -2.0f * __logf(cc); tacc = fmaf(kz, Cv, tacc);
            kz = __uint_as_float(k4.x & 0xFFFF0000u)  * z0.y; racc += kz;
            cc = __cosf(fminf(d0.y * 2.0f, PI2F)) + 1e-5f; Cv = -2.0f * __logf(cc); tacc = fmaf(kz, Cv, tacc);
            kz = __uint_as_float(k4.y << 16)          * z0.z; racc += kz;
            cc = __cosf(fminf(d0.z * 2.0f, PI2F)) + 1e-5f; Cv = -2.0f * __logf(cc); tacc = fmaf(kz, Cv, tacc);
            kz = __uint_as_float(k4.y & 0xFFFF0000u)  * z0.w; racc += kz;
            cc = __cosf(fminf(d0.w * 2.0f, PI2F)) + 1e-5f; Cv = -2.0f * __logf(cc); tacc = fmaf(kz, Cv, tacc);
            kz = __uint_as_float(k4.z << 16)          * z1.x; racc += kz;
            cc = __cosf(fminf(d1.x * 2.0f, PI2F)) + 1e-5f; Cv = -2.0f * __logf(cc); tacc = fmaf(kz, Cv, tacc);
            kz = __uint_as_float(k4.z & 0xFFFF0000u)  * z1.y; racc += kz;
            cc = __cosf(fminf(d1.y * 2.0f, PI2F)) + 1e-5f; Cv = -2.0f * __logf(cc); tacc = fmaf(kz, Cv, tacc);
            kz = __uint_as_float(k4.w << 16)          * z1.z; racc += kz;
            cc = __cosf(fminf(d1.z * 2.0f, PI2F)) + 1e-5f; Cv = -2.0f * __logf(cc); tacc = fmaf(kz, Cv, tacc);
            kz = __uint_as_float(k4.w & 0xFFFF0000u)  * z1.w; racc += kz;
            cc = __cosf(fminf(d1.w * 2.0f, PI2F)) + 1e-5f; Cv = -2.0f * __logf(cc); tacc = fmaf(kz, Cv, tacc);
        }
        sm->part[h][row]     = racc;
        sm->part[2 + h][row] = tacc;
    }
    __syncthreads();

    float val = 0.0f;
    if (t < NN) {
        float w_  = sm->w[t];
        float rm  = DYC * w_ * (sm->part[0][t] + sm->part[1][t]);
        float klr = rm * __logf(rm + 1e-10f) - rm + 1.0f;
        float tp  = w_ * (sm->part[2][t] + sm->part[3][t]) * (DXC * DYC);
        float cm  = DXC * sm->z[t] * sm->csave[t];
        float klc = cm * __logf(cm + 1e-10f) - cm + 1.0f;
        val = klr * DXC + klc * DYC + tp;
    }
    #pragma unroll
    for (int o = 16; o; o >>= 1) val += __shfl_down_sync(0xFFFFFFFFu, val, o);
    if (t < NN && lane == 0) sm->red[wp] = val;
    __syncthreads();
    if (t == 0) {
        float s = 0.0f;
        #pragma unroll
        for (int i = 0; i < 8; i++) s += sm->red[i];
        out[b] = s;
    }
}

extern "C" void kernel_launch(void* const* d_in, const int* in_sizes, int n_in,
                              void* d_out, int out_size)
{
    const float* D = (const float*)d_in[0];
    float* out = (float*)d_out;
    (void)in_sizes; (void)n_in; (void)out_size;
    size_t smem = sizeof(Smem);
    cudaFuncSetAttribute(wfr_kernel, cudaFuncAttributeMaxDynamicSharedMemorySize, (int)smem);
    wfr_kernel<<<NB, 512, smem>>>(D, out);
}